// round 6
// baseline (speedup 1.0000x reference)
#include <cuda_runtime.h>

#define HID 64
#define NB 65536

__device__ float g_x[(size_t)NB * HID];   // conv output [B,64]

// ========================= conv kernel =========================
// 256 threads/block, one batch element per thread.
// shared: weights (10544 floats) + scratch region (256*149 floats) used first
// for coalesced obs staging (stride 147), then per-thread p tiles (stride 149).
#define CT 256
#define CW_FLOATS 10544
#define CP_STRIDE 149
#define CONV_SMEM_FLOATS (CW_FLOATS + CT * CP_STRIDE)
#define CONV_SMEM_BYTES  (CONV_SMEM_FLOATS * 4)   // 194752 bytes

__global__ __launch_bounds__(CT) void conv_k(
    const float* __restrict__ obs,
    const float* __restrict__ w1, const float* __restrict__ b1,
    const float* __restrict__ w2, const float* __restrict__ b2,
    const float* __restrict__ w3, const float* __restrict__ b3)
{
    extern __shared__ float s[];
    float* sw1 = s;            // 192
    float* sb1 = s + 192;      // 16
    float* sw2 = s + 208;      // 2048
    float* sb2 = s + 2256;     // 32
    float* sw3 = s + 2288;     // 8192
    float* sb3 = s + 10480;    // 64
    float* sp  = s + CW_FLOATS;

    const int t = threadIdx.x;
    for (int i = t; i < 192;  i += CT) sw1[i] = w1[i];
    for (int i = t; i < 16;   i += CT) sb1[i] = b1[i];
    for (int i = t; i < 2048; i += CT) sw2[i] = w2[i];
    for (int i = t; i < 32;   i += CT) sb2[i] = b2[i];
    for (int i = t; i < 8192; i += CT) sw3[i] = w3[i];
    for (int i = t; i < 64;   i += CT) sb3[i] = b3[i];

    // coalesced obs staging: 256 rows * 147 floats
    {
        const float4* g = (const float4*)(obs + (size_t)blockIdx.x * CT * 147);
        float4* d = (float4*)sp;
        for (int i = t; i < (CT * 147) / 4; i += CT) d[i] = g[i];
    }
    __syncthreads();

    // per-thread obs row -> regs (stride 147 odd: conflict-free)
    float o[147];
    #pragma unroll 21
    for (int i = 0; i < 147; i++) o[i] = sp[t * 147 + i];
    __syncthreads();   // before overwriting region with p tiles

    // conv1(16,3,2,2) + relu + maxpool2 -> p (shared, stride 149)
    float* pr_ = sp + t * CP_STRIDE;
    #pragma unroll 1
    for (int oc = 0; oc < 16; oc++) {
        const float bias = sb1[oc];
        float wv[12];
        #pragma unroll
        for (int j = 0; j < 12; j++) wv[j] = sw1[oc * 12 + j];
        #pragma unroll
        for (int pi = 0; pi < 3; pi++)
        #pragma unroll
        for (int pj = 0; pj < 3; pj++) {
            float mx = -1e30f;
            #pragma unroll
            for (int di = 0; di < 2; di++)
            #pragma unroll
            for (int dj = 0; dj < 2; dj++) {
                const int i0 = 2 * pi + di, j0 = 2 * pj + dj;
                float acc = bias;
                #pragma unroll
                for (int ic = 0; ic < 3; ic++)
                #pragma unroll
                for (int a = 0; a < 2; a++)
                #pragma unroll
                for (int c = 0; c < 2; c++)
                    acc += o[((i0 + a) * 7 + (j0 + c)) * 3 + ic] * wv[ic * 4 + a * 2 + c];
                mx = fmaxf(mx, acc);
            }
            pr_[oc * 9 + pi * 3 + pj] = fmaxf(mx, 0.f);
        }
    }

    // conv2(32,16,2,2)+relu fused with conv3(64,32,2,2)+relu -> x[64] regs
    float x[64];
    #pragma unroll
    for (int j = 0; j < 64; j++) x[j] = sb3[j];

    const float4* w2v = (const float4*)sw2;
    const float4* w3v = (const float4*)sw3;
    #pragma unroll 1
    for (int oc = 0; oc < 32; oc++) {
        float a0 = sb2[oc], a1 = a0, a2 = a0, a3 = a0;
        #pragma unroll 4
        for (int ic = 0; ic < 16; ic++) {
            const float* pr = pr_ + ic * 9;
            const float p0=pr[0],p1=pr[1],p2=pr[2],p3=pr[3],p4=pr[4],
                        p5=pr[5],p6=pr[6],p7=pr[7],p8=pr[8];
            const float4 w = w2v[oc * 16 + ic];   // broadcast
            a0 += p0*w.x + p1*w.y + p3*w.z + p4*w.w;
            a1 += p1*w.x + p2*w.y + p4*w.z + p5*w.w;
            a2 += p3*w.x + p4*w.y + p6*w.z + p7*w.w;
            a3 += p4*w.x + p5*w.y + p7*w.z + p8*w.w;
        }
        a0 = fmaxf(a0, 0.f); a1 = fmaxf(a1, 0.f);
        a2 = fmaxf(a2, 0.f); a3 = fmaxf(a3, 0.f);
        #pragma unroll
        for (int oc3 = 0; oc3 < 64; oc3++) {
            const float4 w = w3v[oc3 * 32 + oc];  // broadcast
            x[oc3] += a0*w.x + a1*w.y + a2*w.z + a3*w.w;
        }
    }

    const size_t b = (size_t)blockIdx.x * CT + t;
    float4* xo = (float4*)(g_x + b * 64);
    #pragma unroll
    for (int k = 0; k < 16; k++)
        xo[k] = make_float4(fmaxf(x[4*k],0.f), fmaxf(x[4*k+1],0.f),
                            fmaxf(x[4*k+2],0.f), fmaxf(x[4*k+3],0.f));
}

// ========================= GRU + heads kernel (A/B lane-pair) =========================
#define NT2 512
#define NE  256                    // elements per CTA (one per lane pair)
#define RSTRIDE 68                 // floats per element row (<=2-way conflict)
#define SWOFF (NE * RSTRIDE)       // 17408 floats
#define SMEM_FLOATS (SWOFF + 24960)
#define SMEM_BYTES (SMEM_FLOATS * 4)   // 169472 bytes

__device__ __forceinline__ float sigm(float x) {
    return __fdividef(1.f, 1.f + __expf(-x));
}
__device__ __forceinline__ float tanh_fast(float x) {
    float y; asm("tanh.approx.f32 %0, %1;" : "=f"(y) : "f"(x)); return y;
}

__device__ void load_layer(float* sw, const float* wih, const float* whh,
                           const float* bih, const float* bhh)
{
    const int t = threadIdx.x;
    for (int i = t; i < 3072; i += NT2) ((float4*)sw)[i]           = ((const float4*)wih)[i];
    for (int i = t; i < 3072; i += NT2) ((float4*)(sw + 12288))[i] = ((const float4*)whh)[i];
    for (int i = t; i < 48;   i += NT2) ((float4*)(sw + 24576))[i] = ((const float4*)bih)[i];
    for (int i = t; i < 48;   i += NT2) ((float4*)(sw + 24768))[i] = ((const float4*)bhh)[i];
}

// One GRU cell, lane-pair cooperative.
//  A (even lane): v = x, dots vs wih.  B (odd lane): v = h, dots vs whh.
//  B stashes old h in row; A writes new h into row; at end A reloads v=new h.
__device__ void cellAB(float v[64], float* row, const float* sw,
                       const float* __restrict__ hin, const bool isA,
                       float* __restrict__ gout)
{
    float4* row4 = (float4*)row;
    __syncwarp();
    if (!isA) {   // B: load old h -> regs + row stash
        #pragma unroll
        for (int kc = 0; kc < 16; kc++) {
            const float4 f = __ldg((const float4*)hin + kc);
            v[4*kc] = f.x; v[4*kc+1] = f.y; v[4*kc+2] = f.z; v[4*kc+3] = f.w;
            row4[kc] = f;
        }
    }
    __syncwarp();

    const float4* wb = (const float4*)(isA ? sw : sw + 12288);
    const float*  bb = isA ? sw + 24576 : sw + 24768;

    #pragma unroll 1
    for (int o = 0; o < 64; o++) {
        float ar = 0.f, az = 0.f, an = 0.f;
        const float4* wr = wb + o * 16;
        const float4* wz = wr + 64 * 16;
        const float4* wn = wz + 64 * 16;
        #pragma unroll
        for (int kc = 0; kc < 16; kc++) {
            const float4 A = wr[kc], Bv = wz[kc], C = wn[kc];
            const float v0 = v[4*kc], v1 = v[4*kc+1], v2 = v[4*kc+2], v3 = v[4*kc+3];
            ar += v0*A.x  + v1*A.y  + v2*A.z  + v3*A.w;
            az += v0*Bv.x + v1*Bv.y + v2*Bv.z + v3*Bv.w;
            an += v0*C.x  + v1*C.y  + v2*C.z  + v3*C.w;
        }
        ar += bb[o]; az += bb[o + 64]; an += bb[o + 128];
        float ho = 0.f;
        if (!isA) ho = row[o];                    // B reads old h
        const float pr  = __shfl_xor_sync(0xFFFFFFFFu, ar, 1);
        const float pz  = __shfl_xor_sync(0xFFFFFFFFu, az, 1);
        const float pn  = __shfl_xor_sync(0xFFFFFFFFu, an, 1);
        const float pho = __shfl_xor_sync(0xFFFFFFFFu, ho, 1);
        if (isA) {                                // A has B's gh sums + old h
            const float r = sigm(ar + pr);
            const float z = sigm(az + pz);
            const float n = tanh_fast(an + r * pn);
            row[o] = (1.f - z) * n + z * pho;     // new h (after B read old)
        }
    }
    __syncwarp();
    if (isA) {    // A: flush new h + take as next x
        #pragma unroll
        for (int kc = 0; kc < 16; kc++) {
            const float4 f = row4[kc];
            ((float4*)gout)[kc] = f;
            v[4*kc] = f.x; v[4*kc+1] = f.y; v[4*kc+2] = f.z; v[4*kc+3] = f.w;
        }
    }
}

__global__ __launch_bounds__(NT2, 1) void gru_k(
    const float* __restrict__ memory,
    const float* g10a, const float* g10b, const float* g10c, const float* g10d,
    const float* g11a, const float* g11b, const float* g11c, const float* g11d,
    const float* g20a, const float* g20b, const float* g20c, const float* g20d,
    const float* g21a, const float* g21b, const float* g21c, const float* g21d,
    const float* aw1, const float* ab1, const float* aw2, const float* ab2,
    const float* cw1, const float* cb1, const float* cw2, const float* cb2,
    float* __restrict__ out)
{
    extern __shared__ float s[];
    const int t = threadIdx.x;
    const bool isA = ((t & 1) == 0);
    const int e = t >> 1;                          // element in CTA
    const size_t b = (size_t)blockIdx.x * NE + e;
    float* row = s + e * RSTRIDE;
    float* sw  = s + SWOFF;

    float v[64];
    if (isA) {   // A: v = conv output x
        #pragma unroll
        for (int kc = 0; kc < 16; kc++) {
            const float4 f = __ldg((const float4*)(g_x + b * 64) + kc);
            v[4*kc] = f.x; v[4*kc+1] = f.y; v[4*kc+2] = f.z; v[4*kc+3] = f.w;
        }
    }
    const float* mrow = memory + b * 256;
    float* orow = out + (size_t)NB * 4 + b * 256;

    load_layer(sw, g10a, g10b, g10c, g10d);  __syncthreads();
    cellAB(v, row, sw, mrow,       isA, orow);
    __syncthreads(); load_layer(sw, g11a, g11b, g11c, g11d); __syncthreads();
    cellAB(v, row, sw, mrow + 64,  isA, orow + 64);
    __syncthreads(); load_layer(sw, g20a, g20b, g20c, g20d); __syncthreads();
    cellAB(v, row, sw, mrow + 128, isA, orow + 128);
    __syncthreads(); load_layer(sw, g21a, g21b, g21c, g21d); __syncthreads();
    cellAB(v, row, sw, mrow + 192, isA, orow + 192);
    __syncthreads();

    // ---- stage head weights: aw1@0 cw1@4096 ab1@8192 cb1@8256 aw2@8320 ab2@8512 cw2@8516 cb2@8580
    for (int i = t; i < 1024; i += NT2) ((float4*)sw)[i]          = ((const float4*)aw1)[i];
    for (int i = t; i < 1024; i += NT2) ((float4*)(sw + 4096))[i] = ((const float4*)cw1)[i];
    for (int i = t; i < 64;   i += NT2) sw[8192 + i] = ab1[i];
    for (int i = t; i < 64;   i += NT2) sw[8256 + i] = cb1[i];
    for (int i = t; i < 192;  i += NT2) sw[8320 + i] = aw2[i];
    if (t < 3)  sw[8512 + t] = ab2[t];
    for (int i = t; i < 64;   i += NT2) sw[8516 + i] = cw2[i];
    if (t == 0) sw[8580] = cb2[0];
    __syncthreads();

    // B: fetch embedding from row (A already has it in v)
    if (!isA) {
        float4* row4 = (float4*)row;
        #pragma unroll
        for (int kc = 0; kc < 16; kc++) {
            const float4 f = row4[kc];
            v[4*kc] = f.x; v[4*kc+1] = f.y; v[4*kc+2] = f.z; v[4*kc+3] = f.w;
        }
    }

    // hidden layer (A: actor, B: critic), second layer fused into o-loop
    const float4* hw = (const float4*)(isA ? sw : sw + 4096);
    const float*  hb = isA ? sw + 8192 : sw + 8256;
    const float*  l2 = isA ? sw + 8320 : sw + 8516;
    float lg0 = 0.f, lg1 = 0.f, lg2 = 0.f;
    #pragma unroll 1
    for (int o = 0; o < 64; o++) {
        float acc = hb[o];
        const float4* wr = hw + o * 16;
        #pragma unroll
        for (int kc = 0; kc < 16; kc++) {
            const float4 A = wr[kc];
            acc += v[4*kc]*A.x + v[4*kc+1]*A.y + v[4*kc+2]*A.z + v[4*kc+3]*A.w;
        }
        const float h_o = fmaxf(acc, 0.f);
        lg0 += h_o * l2[o];
        if (isA) {
            lg1 += h_o * sw[8384 + o];   // aw2 row 1
            lg2 += h_o * sw[8448 + o];   // aw2 row 2
        }
    }
    if (isA) {
        lg0 += sw[8512]; lg1 += sw[8513]; lg2 += sw[8514];
        const float m = fmaxf(lg0, fmaxf(lg1, lg2));
        const float lse = m + __logf(__expf(lg0 - m) + __expf(lg1 - m) + __expf(lg2 - m));
        out[b*3+0] = lg0 - lse; out[b*3+1] = lg1 - lse; out[b*3+2] = lg2 - lse;
    } else {
        out[(size_t)NB * 3 + b] = lg0 + sw[8580];
    }
}

extern "C" void kernel_launch(void* const* d_in, const int* in_sizes, int n_in,
                              void* d_out, int out_size)
{
    const float* const* in = (const float* const*)d_in;
    cudaFuncSetAttribute(conv_k, cudaFuncAttributeMaxDynamicSharedMemorySize, CONV_SMEM_BYTES);
    conv_k<<<NB / CT, CT, CONV_SMEM_BYTES>>>(in[0], in[2], in[3], in[4], in[5], in[6], in[7]);
    cudaFuncSetAttribute(gru_k, cudaFuncAttributeMaxDynamicSharedMemorySize, SMEM_BYTES);
    gru_k<<<NB / NE, NT2, SMEM_BYTES>>>(in[1],
        in[8],  in[9],  in[10], in[11],
        in[12], in[13], in[14], in[15],
        in[16], in[17], in[18], in[19],
        in[20], in[21], in[22], in[23],
        in[24], in[25], in[26], in[27],
        in[28], in[29], in[30], in[31],
        (float*)d_out);
}